// round 1
// baseline (speedup 1.0000x reference)
#include <cuda_runtime.h>

// VocabularyAttention: out = softmax(x @ Wv^T + bv) @ Wv @ Wl^T + bl
//   x  [M=4096, D=768]   (flattened [B,S,D])
//   Wv [V=50257, D=768]
//   bv [V]
//   Wl [D, D]
//   bl [D]
//   out [M, D] fp32
//
// Fused flash-style kernel: each CTA owns BM=32 query rows, streams the
// vocabulary in BN=64 chunks with online softmax, keeps the 32x768 output
// accumulator in shared memory, then applies the final DxD linear in-kernel.

constexpr int D_DIM    = 768;
constexpr int BM       = 32;
constexpr int BN       = 64;
constexpr int NTHREADS = 256;

constexpr int SQ_LD = 772;   // 768 + 4 pad (bank shift, 16B-aligned rows)
constexpr int SW_LD = 68;    // 64 + 4 pad (16B-aligned rows for LDS.128)
constexpr int SP_LD = 65;

constexpr int SQ_OFF   = 0;
constexpr int SACC_OFF = SQ_OFF   + BM * SQ_LD;   // 24704
constexpr int SW_OFF   = SACC_OFF + BM * SQ_LD;   // 49408
constexpr int SP_OFF   = SW_OFF   + 64 * SW_LD;   // 53760
constexpr int SB_OFF   = SP_OFF   + BM * SP_LD;   // 55840
constexpr int SM_OFF   = SB_OFF   + BN;           // 55904
constexpr int SL_OFF   = SM_OFF   + BM;           // 55936
constexpr int SAL_OFF  = SL_OFF   + BM;           // 55968
constexpr int SMEM_FLOATS = SAL_OFF + BM;         // 56000 floats = 224000 B

__global__ __launch_bounds__(NTHREADS, 1)
void vocab_attn_fused(const float* __restrict__ x,
                      const float* __restrict__ Wv,
                      const float* __restrict__ bv,
                      const float* __restrict__ Wl,
                      const float* __restrict__ bl,
                      float* __restrict__ out,
                      int V)
{
    extern __shared__ float sm[];
    float* sQ   = sm + SQ_OFF;    // [32][772] Q tile (row-major, k fast)
    float* sAcc = sm + SACC_OFF;  // [32][772] output accumulator
    float* sW   = sm + SW_OFF;    // [64][68]  streaming W tile (layout varies)
    float* sP   = sm + SP_OFF;    // [32][65]  logits -> probabilities
    float* sB   = sm + SB_OFF;    // [64]      bias chunk
    float* sMx  = sm + SM_OFF;    // [32] running max
    float* sL   = sm + SL_OFF;    // [32] running denom
    float* sAl  = sm + SAL_OFF;   // [32] rescale factor alpha

    const int tid = threadIdx.x;
    const int tx  = tid & 15;         // 0..15
    const int ty  = tid >> 4;         // 0..15
    const int r0  = ty * 2;           // this thread's 2 rows
    const int c0  = tx * 4;           // this thread's 4 cols
    const int mBase = blockIdx.x * BM;

    // ---- Load Q tile (coalesced), zero accumulator ----
    for (int i = tid; i < BM * D_DIM; i += NTHREADS) {
        int r = i / D_DIM;
        int c = i - r * D_DIM;
        sQ[r * SQ_LD + c]   = x[(size_t)(mBase + r) * D_DIM + c];
        sAcc[r * SQ_LD + c] = 0.0f;
    }
    if (tid < BM) { sMx[tid] = -1e30f; sL[tid] = 0.0f; }
    __syncthreads();

    const int niter = (V + BN - 1) / BN;
    for (int it = 0; it < niter; ++it) {
        const int v0 = it * BN;

        // ======== Phase 1: S[32][64] = Q @ K^T ========
        float s[2][4] = {{0.f,0.f,0.f,0.f},{0.f,0.f,0.f,0.f}};
        for (int k0 = 0; k0 < D_DIM; k0 += 64) {
            // Load K chunk TRANSPOSED: sW[kk][v] so the inner loop can
            // fetch 4 vocab columns with one LDS.128.
            for (int i = tid; i < 64 * 64; i += NTHREADS) {
                int v  = i >> 6;
                int kk = i & 63;
                int gv = v0 + v;
                float val = (gv < V) ? Wv[(size_t)gv * D_DIM + k0 + kk] : 0.0f;
                sW[kk * SW_LD + v] = val;
            }
            __syncthreads();
            #pragma unroll 8
            for (int kk = 0; kk < 64; ++kk) {
                float a0 = sQ[r0 * SQ_LD + k0 + kk];
                float a1 = sQ[r0 * SQ_LD + SQ_LD + k0 + kk];
                float4 b = *reinterpret_cast<const float4*>(sW + kk * SW_LD + c0);
                s[0][0] = fmaf(a0, b.x, s[0][0]);
                s[0][1] = fmaf(a0, b.y, s[0][1]);
                s[0][2] = fmaf(a0, b.z, s[0][2]);
                s[0][3] = fmaf(a0, b.w, s[0][3]);
                s[1][0] = fmaf(a1, b.x, s[1][0]);
                s[1][1] = fmaf(a1, b.y, s[1][1]);
                s[1][2] = fmaf(a1, b.z, s[1][2]);
                s[1][3] = fmaf(a1, b.w, s[1][3]);
            }
            __syncthreads();
        }

        // ---- bias chunk ----
        if (tid < BN) {
            int gv = v0 + tid;
            sB[tid] = (gv < V) ? bv[gv] : 0.0f;
        }
        __syncthreads();

        // ---- write logits (masked) ----
        #pragma unroll
        for (int i = 0; i < 2; ++i) {
            #pragma unroll
            for (int j = 0; j < 4; ++j) {
                int c = c0 + j;
                float val = (v0 + c < V) ? (s[i][j] + sB[c]) : -1e30f;
                sP[(r0 + i) * SP_LD + c] = val;
            }
        }
        __syncthreads();

        // ---- online softmax update (one thread per row) ----
        if (tid < BM) {
            int r = tid;
            float mOld = sMx[r];
            float mx = mOld;
            #pragma unroll 8
            for (int c = 0; c < BN; ++c) mx = fmaxf(mx, sP[r * SP_LD + c]);
            float alpha = __expf(mOld - mx);
            float sum = 0.0f;
            #pragma unroll 8
            for (int c = 0; c < BN; ++c) {
                float p = __expf(sP[r * SP_LD + c] - mx);
                sP[r * SP_LD + c] = p;
                sum += p;
            }
            sL[r]  = sL[r] * alpha + sum;
            sMx[r] = mx;
            sAl[r] = alpha;
        }
        __syncthreads();

        // ======== Phase 2: Acc = Acc*alpha + P @ V ========
        const float al0 = sAl[r0];
        const float al1 = sAl[r0 + 1];
        for (int d0 = 0; d0 < D_DIM; d0 += 64) {
            // Load V chunk natural layout: sW[v][dd]
            for (int i = tid; i < 64 * 64; i += NTHREADS) {
                int v  = i >> 6;
                int dd = i & 63;
                int gv = v0 + v;
                float val = (gv < V) ? Wv[(size_t)gv * D_DIM + d0 + dd] : 0.0f;
                sW[v * SW_LD + dd] = val;
            }
            __syncthreads();
            float c2[2][4] = {{0.f,0.f,0.f,0.f},{0.f,0.f,0.f,0.f}};
            #pragma unroll 8
            for (int vv = 0; vv < 64; ++vv) {
                float a0 = sP[r0 * SP_LD + vv];
                float a1 = sP[(r0 + 1) * SP_LD + vv];
                float4 b = *reinterpret_cast<const float4*>(sW + vv * SW_LD + c0);
                c2[0][0] = fmaf(a0, b.x, c2[0][0]);
                c2[0][1] = fmaf(a0, b.y, c2[0][1]);
                c2[0][2] = fmaf(a0, b.z, c2[0][2]);
                c2[0][3] = fmaf(a0, b.w, c2[0][3]);
                c2[1][0] = fmaf(a1, b.x, c2[1][0]);
                c2[1][1] = fmaf(a1, b.y, c2[1][1]);
                c2[1][2] = fmaf(a1, b.z, c2[1][2]);
                c2[1][3] = fmaf(a1, b.w, c2[1][3]);
            }
            // fold alpha rescale into the accumulate (each (r,c) touched
            // exactly once per outer iteration)
            #pragma unroll
            for (int j = 0; j < 4; ++j) {
                int c = d0 + c0 + j;
                sAcc[r0 * SQ_LD + c] =
                    sAcc[r0 * SQ_LD + c] * al0 + c2[0][j];
                sAcc[r0 * SQ_LD + SQ_LD + c] =
                    sAcc[r0 * SQ_LD + SQ_LD + c] * al1 + c2[1][j];
            }
            __syncthreads();
        }
    }

    // ---- normalize: h = acc / l ----
    for (int i = tid; i < BM * D_DIM; i += NTHREADS) {
        int r = i / D_DIM;
        int c = i - r * D_DIM;
        sAcc[r * SQ_LD + c] = sAcc[r * SQ_LD + c] / sL[r];
    }
    __syncthreads();

    // ======== Epilogue: out = h @ Wl^T + bl ========
    for (int e0 = 0; e0 < D_DIM; e0 += 64) {
        float o[2][4] = {{0.f,0.f,0.f,0.f},{0.f,0.f,0.f,0.f}};
        for (int d0 = 0; d0 < D_DIM; d0 += 64) {
            // Load Wl tile [e][dd]
            for (int i = tid; i < 64 * 64; i += NTHREADS) {
                int e  = i >> 6;
                int dd = i & 63;
                sW[e * SW_LD + dd] = Wl[(size_t)(e0 + e) * D_DIM + d0 + dd];
            }
            __syncthreads();
            #pragma unroll 8
            for (int dd = 0; dd < 64; ++dd) {
                float a0 = sAcc[r0 * SQ_LD + d0 + dd];
                float a1 = sAcc[r0 * SQ_LD + SQ_LD + d0 + dd];
                float b0 = sW[(c0 + 0) * SW_LD + dd];
                float b1 = sW[(c0 + 1) * SW_LD + dd];
                float b2 = sW[(c0 + 2) * SW_LD + dd];
                float b3 = sW[(c0 + 3) * SW_LD + dd];
                o[0][0] = fmaf(a0, b0, o[0][0]);
                o[0][1] = fmaf(a0, b1, o[0][1]);
                o[0][2] = fmaf(a0, b2, o[0][2]);
                o[0][3] = fmaf(a0, b3, o[0][3]);
                o[1][0] = fmaf(a1, b0, o[1][0]);
                o[1][1] = fmaf(a1, b1, o[1][1]);
                o[1][2] = fmaf(a1, b2, o[1][2]);
                o[1][3] = fmaf(a1, b3, o[1][3]);
            }
            __syncthreads();
        }
        #pragma unroll
        for (int j = 0; j < 4; ++j) {
            int e = e0 + c0 + j;
            float bb = bl[e];
            out[(size_t)(mBase + r0) * D_DIM + e]     = o[0][j] + bb;
            out[(size_t)(mBase + r0 + 1) * D_DIM + e] = o[1][j] + bb;
        }
    }
}

extern "C" void kernel_launch(void* const* d_in, const int* in_sizes, int n_in,
                              void* d_out, int out_size)
{
    const float* x  = (const float*)d_in[0];
    const float* Wv = (const float*)d_in[1];
    const float* bv = (const float*)d_in[2];
    const float* Wl = (const float*)d_in[3];
    const float* bl = (const float*)d_in[4];
    float* out = (float*)d_out;

    const int V = in_sizes[2];            // b_vocab length = 50257
    const int M = in_sizes[0] / D_DIM;    // 4096 query rows

    const size_t smemBytes = SMEM_FLOATS * sizeof(float);  // 224000 B
    cudaFuncSetAttribute(vocab_attn_fused,
                         cudaFuncAttributeMaxDynamicSharedMemorySize,
                         (int)smemBytes);

    vocab_attn_fused<<<M / BM, NTHREADS, smemBytes>>>(x, Wv, bv, Wl, bl, out, V);
}

// round 2
// speedup vs baseline: 1.0016x; 1.0016x over previous
#include <cuda_runtime.h>

// VocabularyAttention: out = softmax(x @ Wv^T + bv) @ Wv @ Wl^T + bl
//   x  [M=4096, D=768]   (flattened [B,S,D])
//   Wv [V=50257, D=768]
//   bv [V]
//   Wl [D, D]
//   bl [D]
//   out [M, D] fp32
//
// Fused flash-style kernel: each CTA owns BM=32 query rows, streams the
// vocabulary in BN=64 chunks with online softmax, keeps the 32x768 output
// accumulator in shared memory, then applies the final DxD linear in-kernel.

constexpr int D_DIM    = 768;
constexpr int BM       = 32;
constexpr int BN       = 64;
constexpr int NTHREADS = 256;

constexpr int SQ_LD = 772;   // 768 + 4 pad (bank shift, 16B-aligned rows)
constexpr int SW_LD = 68;    // 64 + 4 pad (16B-aligned rows for LDS.128)
constexpr int SP_LD = 65;

constexpr int SQ_OFF   = 0;
constexpr int SACC_OFF = SQ_OFF   + BM * SQ_LD;   // 24704
constexpr int SW_OFF   = SACC_OFF + BM * SQ_LD;   // 49408
constexpr int SP_OFF   = SW_OFF   + 64 * SW_LD;   // 53760
constexpr int SB_OFF   = SP_OFF   + BM * SP_LD;   // 55840
constexpr int SM_OFF   = SB_OFF   + BN;           // 55904
constexpr int SL_OFF   = SM_OFF   + BM;           // 55936
constexpr int SAL_OFF  = SL_OFF   + BM;           // 55968
constexpr int SMEM_FLOATS = SAL_OFF + BM;         // 56000 floats = 224000 B

__global__ __launch_bounds__(NTHREADS, 1)
void vocab_attn_fused(const float* __restrict__ x,
                      const float* __restrict__ Wv,
                      const float* __restrict__ bv,
                      const float* __restrict__ Wl,
                      const float* __restrict__ bl,
                      float* __restrict__ out,
                      int V)
{
    extern __shared__ float sm[];
    float* sQ   = sm + SQ_OFF;    // [32][772] Q tile (row-major, k fast)
    float* sAcc = sm + SACC_OFF;  // [32][772] output accumulator
    float* sW   = sm + SW_OFF;    // [64][68]  streaming W tile (layout varies)
    float* sP   = sm + SP_OFF;    // [32][65]  logits -> probabilities
    float* sB   = sm + SB_OFF;    // [64]      bias chunk
    float* sMx  = sm + SM_OFF;    // [32] running max
    float* sL   = sm + SL_OFF;    // [32] running denom
    float* sAl  = sm + SAL_OFF;   // [32] rescale factor alpha

    const int tid = threadIdx.x;
    const int tx  = tid & 15;         // 0..15
    const int ty  = tid >> 4;         // 0..15
    const int r0  = ty * 2;           // this thread's 2 rows
    const int c0  = tx * 4;           // this thread's 4 cols
    const int mBase = blockIdx.x * BM;

    // ---- Load Q tile (coalesced), zero accumulator ----
    for (int i = tid; i < BM * D_DIM; i += NTHREADS) {
        int r = i / D_DIM;
        int c = i - r * D_DIM;
        sQ[r * SQ_LD + c]   = x[(size_t)(mBase + r) * D_DIM + c];
        sAcc[r * SQ_LD + c] = 0.0f;
    }
    if (tid < BM) { sMx[tid] = -1e30f; sL[tid] = 0.0f; }
    __syncthreads();

    const int niter = (V + BN - 1) / BN;
    for (int it = 0; it < niter; ++it) {
        const int v0 = it * BN;

        // ======== Phase 1: S[32][64] = Q @ K^T ========
        float s[2][4] = {{0.f,0.f,0.f,0.f},{0.f,0.f,0.f,0.f}};
        for (int k0 = 0; k0 < D_DIM; k0 += 64) {
            // Load K chunk TRANSPOSED: sW[kk][v] so the inner loop can
            // fetch 4 vocab columns with one LDS.128.
            for (int i = tid; i < 64 * 64; i += NTHREADS) {
                int v  = i >> 6;
                int kk = i & 63;
                int gv = v0 + v;
                float val = (gv < V) ? Wv[(size_t)gv * D_DIM + k0 + kk] : 0.0f;
                sW[kk * SW_LD + v] = val;
            }
            __syncthreads();
            #pragma unroll 8
            for (int kk = 0; kk < 64; ++kk) {
                float a0 = sQ[r0 * SQ_LD + k0 + kk];
                float a1 = sQ[r0 * SQ_LD + SQ_LD + k0 + kk];
                float4 b = *reinterpret_cast<const float4*>(sW + kk * SW_LD + c0);
                s[0][0] = fmaf(a0, b.x, s[0][0]);
                s[0][1] = fmaf(a0, b.y, s[0][1]);
                s[0][2] = fmaf(a0, b.z, s[0][2]);
                s[0][3] = fmaf(a0, b.w, s[0][3]);
                s[1][0] = fmaf(a1, b.x, s[1][0]);
                s[1][1] = fmaf(a1, b.y, s[1][1]);
                s[1][2] = fmaf(a1, b.z, s[1][2]);
                s[1][3] = fmaf(a1, b.w, s[1][3]);
            }
            __syncthreads();
        }

        // ---- bias chunk ----
        if (tid < BN) {
            int gv = v0 + tid;
            sB[tid] = (gv < V) ? bv[gv] : 0.0f;
        }
        __syncthreads();

        // ---- write logits (masked) ----
        #pragma unroll
        for (int i = 0; i < 2; ++i) {
            #pragma unroll
            for (int j = 0; j < 4; ++j) {
                int c = c0 + j;
                float val = (v0 + c < V) ? (s[i][j] + sB[c]) : -1e30f;
                sP[(r0 + i) * SP_LD + c] = val;
            }
        }
        __syncthreads();

        // ---- online softmax update (one thread per row) ----
        if (tid < BM) {
            int r = tid;
            float mOld = sMx[r];
            float mx = mOld;
            #pragma unroll 8
            for (int c = 0; c < BN; ++c) mx = fmaxf(mx, sP[r * SP_LD + c]);
            float alpha = __expf(mOld - mx);
            float sum = 0.0f;
            #pragma unroll 8
            for (int c = 0; c < BN; ++c) {
                float p = __expf(sP[r * SP_LD + c] - mx);
                sP[r * SP_LD + c] = p;
                sum += p;
            }
            sL[r]  = sL[r] * alpha + sum;
            sMx[r] = mx;
            sAl[r] = alpha;
        }
        __syncthreads();

        // ======== Phase 2: Acc = Acc*alpha + P @ V ========
        const float al0 = sAl[r0];
        const float al1 = sAl[r0 + 1];
        for (int d0 = 0; d0 < D_DIM; d0 += 64) {
            // Load V chunk natural layout: sW[v][dd]
            for (int i = tid; i < 64 * 64; i += NTHREADS) {
                int v  = i >> 6;
                int dd = i & 63;
                int gv = v0 + v;
                float val = (gv < V) ? Wv[(size_t)gv * D_DIM + d0 + dd] : 0.0f;
                sW[v * SW_LD + dd] = val;
            }
            __syncthreads();
            float c2[2][4] = {{0.f,0.f,0.f,0.f},{0.f,0.f,0.f,0.f}};
            #pragma unroll 8
            for (int vv = 0; vv < 64; ++vv) {
                float a0 = sP[r0 * SP_LD + vv];
                float a1 = sP[(r0 + 1) * SP_LD + vv];
                float4 b = *reinterpret_cast<const float4*>(sW + vv * SW_LD + c0);
                c2[0][0] = fmaf(a0, b.x, c2[0][0]);
                c2[0][1] = fmaf(a0, b.y, c2[0][1]);
                c2[0][2] = fmaf(a0, b.z, c2[0][2]);
                c2[0][3] = fmaf(a0, b.w, c2[0][3]);
                c2[1][0] = fmaf(a1, b.x, c2[1][0]);
                c2[1][1] = fmaf(a1, b.y, c2[1][1]);
                c2[1][2] = fmaf(a1, b.z, c2[1][2]);
                c2[1][3] = fmaf(a1, b.w, c2[1][3]);
            }
            // fold alpha rescale into the accumulate (each (r,c) touched
            // exactly once per outer iteration)
            #pragma unroll
            for (int j = 0; j < 4; ++j) {
                int c = d0 + c0 + j;
                sAcc[r0 * SQ_LD + c] =
                    sAcc[r0 * SQ_LD + c] * al0 + c2[0][j];
                sAcc[r0 * SQ_LD + SQ_LD + c] =
                    sAcc[r0 * SQ_LD + SQ_LD + c] * al1 + c2[1][j];
            }
            __syncthreads();
        }
    }

    // ---- normalize: h = acc / l ----
    for (int i = tid; i < BM * D_DIM; i += NTHREADS) {
        int r = i / D_DIM;
        int c = i - r * D_DIM;
        sAcc[r * SQ_LD + c] = sAcc[r * SQ_LD + c] / sL[r];
    }
    __syncthreads();

    // ======== Epilogue: out = h @ Wl^T + bl ========
    for (int e0 = 0; e0 < D_DIM; e0 += 64) {
        float o[2][4] = {{0.f,0.f,0.f,0.f},{0.f,0.f,0.f,0.f}};
        for (int d0 = 0; d0 < D_DIM; d0 += 64) {
            // Load Wl tile [e][dd]
            for (int i = tid; i < 64 * 64; i += NTHREADS) {
                int e  = i >> 6;
                int dd = i & 63;
                sW[e * SW_LD + dd] = Wl[(size_t)(e0 + e) * D_DIM + d0 + dd];
            }
            __syncthreads();
            #pragma unroll 8
            for (int dd = 0; dd < 64; ++dd) {
                float a0 = sAcc[r0 * SQ_LD + d0 + dd];
                float a1 = sAcc[r0 * SQ_LD + SQ_LD + d0 + dd];
                float b0 = sW[(c0 + 0) * SW_LD + dd];
                float b1 = sW[(c0 + 1) * SW_LD + dd];
                float b2 = sW[(c0 + 2) * SW_LD + dd];
                float b3 = sW[(c0 + 3) * SW_LD + dd];
                o[0][0] = fmaf(a0, b0, o[0][0]);
                o[0][1] = fmaf(a0, b1, o[0][1]);
                o[0][2] = fmaf(a0, b2, o[0][2]);
                o[0][3] = fmaf(a0, b3, o[0][3]);
                o[1][0] = fmaf(a1, b0, o[1][0]);
                o[1][1] = fmaf(a1, b1, o[1][1]);
                o[1][2] = fmaf(a1, b2, o[1][2]);
                o[1][3] = fmaf(a1, b3, o[1][3]);
            }
            __syncthreads();
        }
        #pragma unroll
        for (int j = 0; j < 4; ++j) {
            int e = e0 + c0 + j;
            float bb = bl[e];
            out[(size_t)(mBase + r0) * D_DIM + e]     = o[0][j] + bb;
            out[(size_t)(mBase + r0 + 1) * D_DIM + e] = o[1][j] + bb;
        }
    }
}

extern "C" void kernel_launch(void* const* d_in, const int* in_sizes, int n_in,
                              void* d_out, int out_size)
{
    const float* x  = (const float*)d_in[0];
    const float* Wv = (const float*)d_in[1];
    const float* bv = (const float*)d_in[2];
    const float* Wl = (const float*)d_in[3];
    const float* bl = (const float*)d_in[4];
    float* out = (float*)d_out;

    const int V = in_sizes[2];            // b_vocab length = 50257
    const int M = in_sizes[0] / D_DIM;    // 4096 query rows

    const size_t smemBytes = SMEM_FLOATS * sizeof(float);  // 224000 B
    cudaFuncSetAttribute(vocab_attn_fused,
                         cudaFuncAttributeMaxDynamicSharedMemorySize,
                         (int)smemBytes);

    vocab_attn_fused<<<M / BM, NTHREADS, smemBytes>>>(x, Wv, bv, Wl, bl, out, V);
}

// round 4
// speedup vs baseline: 9.7520x; 9.7367x over previous
#include <cuda_runtime.h>
#include <cstdint>

// ============================================================================
// VocabularyAttention on GB300 (sm_103a) via family-portable tensor-core path
// (mma.sync.m16n8k8 tf32 + cp.async; tcgen05 PTX is rejected by the harness's
// plain compute_103 target).
//
//   1. WvT = transpose(Wv)                          (pad V -> VPAD with zeros)
//   2. logits = x @ Wv^T + bv                       (mma tf32; pad -> -1e30)
//   3. rowwise softmax in place: p = exp(x-m)/l     (1/l folded into write)
//   4. h = P @ WvT^T                                (mma tf32)
//   5. out = h @ Wl^T + bl                          (mma tf32)
// ============================================================================

#define VOCAB 50257
#define VPAD  50432      // 394*128 ; multiple of 128 and 32
#define DDIM  768
#define MROWS 4096

__device__ float g_probs[(size_t)MROWS * VPAD];   // ~826 MB
__device__ float g_wvt[(size_t)DDIM * VPAD];      // ~155 MB
__device__ float g_h[(size_t)MROWS * DDIM];       // ~12.6 MB
__device__ float g_rln[MROWS];

// ---------------------------------------------------------------------------
__device__ __forceinline__ uint32_t smem_u32(const void* p) {
    uint32_t a;
    asm("{ .reg .u64 t; cvta.to.shared.u64 t, %1; cvt.u32.u64 %0, t; }"
        : "=r"(a) : "l"(p));
    return a;
}

__device__ __forceinline__ uint32_t f2tf32(float f) {
    uint32_t r;
    asm("cvt.rna.tf32.f32 %0, %1;" : "=r"(r) : "f"(f));
    return r;
}

__device__ __forceinline__ void mma_tf32(float c[4],
                                         uint32_t a0, uint32_t a1,
                                         uint32_t a2, uint32_t a3,
                                         uint32_t b0, uint32_t b1) {
    asm volatile(
        "mma.sync.aligned.m16n8k8.row.col.f32.tf32.tf32.f32 "
        "{%0,%1,%2,%3}, {%4,%5,%6,%7}, {%8,%9}, {%0,%1,%2,%3};"
        : "+f"(c[0]), "+f"(c[1]), "+f"(c[2]), "+f"(c[3])
        : "r"(a0), "r"(a1), "r"(a2), "r"(a3), "r"(b0), "r"(b1));
}

// ============================================================================
// Canonical GEMM:  C[M,N] = A[M,K] @ B[N,K]^T  (both row-major / K-major)
// CTA tile 128x128, BK=32, 8 warps (2m x 4n), warp tile 64x32.
// Double-buffered cp.async pipeline. B rows >= nvalidB are zero-filled.
// epi_mode: 0 = +aux[col], cols >= nvalidB -> -1e30   (logits)
//           2 = +aux[col]                             (final bias)
//           3 = plain store                           (h)
// ============================================================================
constexpr int BK     = 32;
constexpr int LDS_F  = 36;            // floats per smem row (conflict-free)
constexpr int TILE_F = 128 * LDS_F;   // 4608 floats per tile-stage

__global__ void __launch_bounds__(256, 2)
gemm_tn(const float* __restrict__ A, long long lda,
        const float* __restrict__ B, long long ldb,
        float* __restrict__ C, long long ldc,
        int K, int nvalidB,
        const float* __restrict__ aux, int epi_mode)
{
    extern __shared__ float sm[];
    float* sA = sm;                 // [2][128][36]
    float* sB = sm + 2 * TILE_F;    // [2][128][36]

    const int tid  = threadIdx.x;
    const int wid  = tid >> 5;
    const int lane = tid & 31;
    const int g    = lane >> 2;     // group id 0..7
    const int t    = lane & 3;      // thread-in-group 0..3
    const int wm   = wid >> 2;      // 0..1  (m)
    const int wn   = wid & 3;       // 0..3  (n)
    const int m0   = blockIdx.x * 128;
    const int n0   = blockIdx.y * 128;

    // ---- tile loader: 256 thr * 4 float4 per operand ----
    auto load_tiles = [&](int c, int s) {
        const float* Ab = A + (size_t)m0 * lda + (size_t)c * BK;
        const uint32_t sAa = smem_u32(sA + s * TILE_F);
        const uint32_t sBa = smem_u32(sB + s * TILE_F);
        #pragma unroll
        for (int q = 0; q < 4; ++q) {
            int idx = tid + q * 256;
            int r = idx >> 3, j = idx & 7;
            const float* gp = Ab + (size_t)r * lda + j * 4;
            uint32_t da = sAa + (uint32_t)(r * LDS_F + j * 4) * 4;
            asm volatile("cp.async.cg.shared.global [%0], [%1], 16;"
                         :: "r"(da), "l"(gp) : "memory");
            int gn = n0 + r;
            int ok = (gn < nvalidB);
            const float* gq = B + (size_t)(ok ? gn : 0) * ldb
                              + (size_t)c * BK + j * 4;
            uint32_t db = sBa + (uint32_t)(r * LDS_F + j * 4) * 4;
            int sz = ok ? 16 : 0;
            asm volatile("cp.async.cg.shared.global [%0], [%1], 16, %2;"
                         :: "r"(db), "l"(gq), "r"(sz) : "memory");
        }
        asm volatile("cp.async.commit_group;" ::: "memory");
    };

    float acc[4][4][4];
    #pragma unroll
    for (int i = 0; i < 4; ++i)
        #pragma unroll
        for (int j = 0; j < 4; ++j)
            #pragma unroll
            for (int k = 0; k < 4; ++k) acc[i][j][k] = 0.f;

    load_tiles(0, 0);
    const int NCH = K / BK;

    for (int c = 0; c < NCH; ++c) {
        const int s = c & 1;
        if (c + 1 < NCH) {
            load_tiles(c + 1, s ^ 1);
            asm volatile("cp.async.wait_group 1;" ::: "memory");
        } else {
            asm volatile("cp.async.wait_group 0;" ::: "memory");
        }
        __syncthreads();

        const float* tA = sA + s * TILE_F;
        const float* tB = sB + s * TILE_F;

        #pragma unroll
        for (int ks = 0; ks < 4; ++ks) {           // 4 x (k=8) per BK=32
            const int kb = ks * 8;
            uint32_t bf[4][2];
            #pragma unroll
            for (int ni = 0; ni < 4; ++ni) {
                int col = wn * 32 + ni * 8 + g;
                bf[ni][0] = f2tf32(tB[col * LDS_F + kb + t]);
                bf[ni][1] = f2tf32(tB[col * LDS_F + kb + t + 4]);
            }
            #pragma unroll
            for (int mi = 0; mi < 4; ++mi) {
                int rr = wm * 64 + mi * 16 + g;
                uint32_t a0 = f2tf32(tA[rr * LDS_F + kb + t]);
                uint32_t a1 = f2tf32(tA[(rr + 8) * LDS_F + kb + t]);
                uint32_t a2 = f2tf32(tA[rr * LDS_F + kb + t + 4]);
                uint32_t a3 = f2tf32(tA[(rr + 8) * LDS_F + kb + t + 4]);
                #pragma unroll
                for (int ni = 0; ni < 4; ++ni)
                    mma_tf32(acc[mi][ni], a0, a1, a2, a3, bf[ni][0], bf[ni][1]);
            }
        }
        __syncthreads();
    }

    // ---- epilogue ----
    #pragma unroll
    for (int mi = 0; mi < 4; ++mi) {
        const int rr = m0 + wm * 64 + mi * 16 + g;
        #pragma unroll
        for (int ni = 0; ni < 4; ++ni) {
            const int col = n0 + wn * 32 + ni * 8 + 2 * t;
            float v0 = acc[mi][ni][0], v1 = acc[mi][ni][1];
            float v2 = acc[mi][ni][2], v3 = acc[mi][ni][3];
            if (epi_mode == 0) {
                float b0 = aux[col], b1 = aux[col + 1];
                v0 += b0; v1 += b1; v2 += b0; v3 += b1;
                if (col     >= nvalidB) { v0 = -1e30f; v2 = -1e30f; }
                if (col + 1 >= nvalidB) { v1 = -1e30f; v3 = -1e30f; }
            } else if (epi_mode == 2) {
                float b0 = aux[col], b1 = aux[col + 1];
                v0 += b0; v1 += b1; v2 += b0; v3 += b1;
            }
            *reinterpret_cast<float2*>(C + (size_t)rr * ldc + col) =
                make_float2(v0, v1);
            *reinterpret_cast<float2*>(C + (size_t)(rr + 8) * ldc + col) =
                make_float2(v2, v3);
        }
    }
}

// ============================================================================
// WvT[d, v] = Wv[v, d], zero-padded to VPAD columns
// ============================================================================
__global__ void __launch_bounds__(256)
transpose_wv(const float* __restrict__ Wv, float* __restrict__ WvT)
{
    __shared__ float tt[32][33];
    const int v0 = blockIdx.x * 32;
    const int d0 = blockIdx.y * 32;
    const int tx = threadIdx.x & 31;
    const int ty = threadIdx.x >> 5;     // 0..7
    #pragma unroll
    for (int i = 0; i < 32; i += 8) {
        int v = v0 + ty + i;
        tt[ty + i][tx] = (v < VOCAB) ? Wv[(size_t)v * DDIM + d0 + tx] : 0.f;
    }
    __syncthreads();
    #pragma unroll
    for (int i = 0; i < 32; i += 8)
        WvT[(size_t)(d0 + ty + i) * VPAD + v0 + tx] = tt[tx][ty + i];
}

// ============================================================================
// Row softmax: online (m, l), then write p = exp(x - m) * (1/l) in place.
// Pad cols hold -1e30 -> exp underflows to exactly 0.
// ============================================================================
__global__ void __launch_bounds__(256)
softmax_rows(float* __restrict__ L, float* __restrict__ rln_out)
{
    __shared__ float sm_m[256], sm_s[256];
    const int row = blockIdx.x;
    float* rp = L + (size_t)row * VPAD;
    const int tid = threadIdx.x;

    float m = -3.0e38f, s = 0.f;
    for (int i = tid; i < VPAD / 4; i += 256) {
        float4 v = reinterpret_cast<const float4*>(rp)[i];
        float xs[4] = {v.x, v.y, v.z, v.w};
        #pragma unroll
        for (int q = 0; q < 4; ++q) {
            float x = xs[q];
            if (x > m) { s = s * __expf(m - x) + 1.f; m = x; }
            else       { s += __expf(x - m); }
        }
    }
    sm_m[tid] = m; sm_s[tid] = s;
    __syncthreads();
    for (int off = 128; off > 0; off >>= 1) {
        if (tid < off) {
            float m2 = sm_m[tid + off], s2 = sm_s[tid + off];
            float m1 = sm_m[tid],       s1 = sm_s[tid];
            float M = fmaxf(m1, m2);
            sm_s[tid] = s1 * __expf(m1 - M) + s2 * __expf(m2 - M);
            sm_m[tid] = M;
        }
        __syncthreads();
    }
    const float M = sm_m[0];
    const float R = 1.0f / sm_s[0];
    if (tid == 0) rln_out[row] = R;

    for (int i = tid; i < VPAD / 4; i += 256) {
        float4 v = reinterpret_cast<const float4*>(rp)[i];
        v.x = __expf(v.x - M) * R;
        v.y = __expf(v.y - M) * R;
        v.z = __expf(v.z - M) * R;
        v.w = __expf(v.w - M) * R;
        reinterpret_cast<float4*>(rp)[i] = v;
    }
}

// ============================================================================
// host launcher
// ============================================================================
extern "C" void kernel_launch(void* const* d_in, const int* in_sizes, int n_in,
                              void* d_out, int out_size)
{
    const float* x  = (const float*)d_in[0];
    const float* Wv = (const float*)d_in[1];
    const float* bv = (const float*)d_in[2];
    const float* Wl = (const float*)d_in[3];
    const float* bl = (const float*)d_in[4];
    float* out = (float*)d_out;

    void *p_probs, *p_wvt, *p_h, *p_rln;
    cudaGetSymbolAddress(&p_probs, g_probs);
    cudaGetSymbolAddress(&p_wvt,   g_wvt);
    cudaGetSymbolAddress(&p_h,     g_h);
    cudaGetSymbolAddress(&p_rln,   g_rln);
    float* probs = (float*)p_probs;
    float* wvt   = (float*)p_wvt;
    float* h     = (float*)p_h;

    const int SMEM = 4 * TILE_F * sizeof(float);  // 73728 B
    static bool attr_set = false;
    if (!attr_set) {
        cudaFuncSetAttribute(gemm_tn,
            cudaFuncAttributeMaxDynamicSharedMemorySize, SMEM);
        attr_set = true;
    }

    // 1) WvT = Wv^T (padded)
    transpose_wv<<<dim3(VPAD / 32, DDIM / 32), 256>>>(Wv, wvt);

    // 2) logits = x @ Wv^T + bv   [4096, VPAD], pad cols -> -1e30
    gemm_tn<<<dim3(MROWS / 128, VPAD / 128), 256, SMEM>>>(
        x, DDIM, Wv, DDIM, probs, VPAD, DDIM, VOCAB, bv, 0);

    // 3) softmax in place (1/l folded into probs)
    softmax_rows<<<MROWS, 256>>>(probs, (float*)p_rln);

    // 4) h = P @ Wv  (B = WvT, K = VPAD)
    gemm_tn<<<dim3(MROWS / 128, DDIM / 128), 256, SMEM>>>(
        probs, VPAD, wvt, VPAD, h, DDIM, VPAD, DDIM, nullptr, 3);

    // 5) out = h @ Wl^T + bl
    gemm_tn<<<dim3(MROWS / 128, DDIM / 128), 256, SMEM>>>(
        h, DDIM, Wl, DDIM, out, DDIM, DDIM, DDIM, bl, 2);
}

// round 5
// speedup vs baseline: 12.4083x; 1.2724x over previous
#include <cuda_runtime.h>
#include <cstdint>

// ============================================================================
// VocabularyAttention on GB300 (sm_103a), mma.sync m16n8k8 tf32 + cp.async.
// All GEMM operands are PRE-ROUNDED to tf32 (prep kernels / producer
// epilogues), so the GEMM mainloop has zero cvt instructions.
//
//   1. xr  = round(x); wlr = round(Wl); {wvt, wvr} = round(Wv) (+transpose)
//   2. logits = xr @ wvr^T + bv            (pad cols -> -1e30)
//   3. softmax rows in place, p = round(exp(x-m)/l)
//   4. hp[z] = p @ wvt^T  (split-K=4);  h = round(sum hp)
//   5. out = h @ wlr^T + bl
// ============================================================================

#define VOCAB 50257
#define VPAD  50432      // 197*256
#define DDIM  768
#define MROWS 4096
#define SPLITK 4
#define KSPLIT (VPAD / SPLITK)   // 12608 = 394*32

__device__ float g_probs[(size_t)MROWS * VPAD];    // ~826 MB
__device__ float g_wvt[(size_t)DDIM * VPAD];       // ~155 MB (rounded, padded)
__device__ float g_wvr[(size_t)VOCAB * DDIM];      // ~154 MB (rounded copy)
__device__ float g_xr[(size_t)MROWS * DDIM];
__device__ float g_wlr[(size_t)DDIM * DDIM];
__device__ float g_hp[(size_t)SPLITK * MROWS * DDIM];
__device__ float g_h[(size_t)MROWS * DDIM];

// ---------------------------------------------------------------------------
__device__ __forceinline__ uint32_t smem_u32(const void* p) {
    uint32_t a;
    asm("{ .reg .u64 t; cvta.to.shared.u64 t, %1; cvt.u32.u64 %0, t; }"
        : "=r"(a) : "l"(p));
    return a;
}

__device__ __forceinline__ float tf32r(float f) {
    uint32_t r;
    asm("cvt.rna.tf32.f32 %0, %1;" : "=r"(r) : "f"(f));
    return __uint_as_float(r);
}

__device__ __forceinline__ void mma_tf32(float c[4],
                                         uint32_t a0, uint32_t a1,
                                         uint32_t a2, uint32_t a3,
                                         uint32_t b0, uint32_t b1) {
    asm volatile(
        "mma.sync.aligned.m16n8k8.row.col.f32.tf32.tf32.f32 "
        "{%0,%1,%2,%3}, {%4,%5,%6,%7}, {%8,%9}, {%0,%1,%2,%3};"
        : "+f"(c[0]), "+f"(c[1]), "+f"(c[2]), "+f"(c[3])
        : "r"(a0), "r"(a1), "r"(a2), "r"(a3), "r"(b0), "r"(b1));
}

// ============================================================================
// GEMM:  C[M,N] = A[M,K] @ B[N,K]^T   (row-major / K-major, pre-rounded tf32)
// CTA tile 128x256, 8 warps (2m x 4n), warp tile 64x64, BK=32,
// 3-stage cp.async pipeline. blockIdx.z = split-K slice.
// epi_mode: 0 = +aux[col], cols >= nvalidB -> -1e30   (logits)
//           2 = +aux[col]                             (final bias)
//           3 = plain store                           (split-K partials)
// ============================================================================
constexpr int BK      = 32;
constexpr int LDS_F   = 36;               // 36 = 4 (mod 32) -> conflict-free
constexpr int A_STAGE = 128 * LDS_F;      // 4608 floats
constexpr int B_STAGE = 256 * LDS_F;      // 9216 floats
constexpr int NSTAGE  = 3;
constexpr int GEMM_SMEM = NSTAGE * (A_STAGE + B_STAGE) * 4;   // 165888 B

__global__ void __launch_bounds__(256, 1)
gemm_tn(const float* __restrict__ A, long long lda,
        const float* __restrict__ B, long long ldb,
        float* __restrict__ C, long long ldc, long long c_zstride,
        int Kps, int nvalidB,
        const float* __restrict__ aux, int epi_mode)
{
    extern __shared__ float sm[];
    float* sA = sm;                          // [3][128][36]
    float* sB = sm + NSTAGE * A_STAGE;       // [3][256][36]

    const int tid  = threadIdx.x;
    const int wid  = tid >> 5;
    const int lane = tid & 31;
    const int g    = lane >> 2;      // 0..7
    const int t    = lane & 3;       // 0..3
    const int wm   = wid >> 2;       // 0..1
    const int wn   = wid & 3;        // 0..3
    const int m0   = blockIdx.x * 128;
    const int n0   = blockIdx.y * 256;

    const long long koff = (long long)blockIdx.z * Kps;
    A += koff;
    B += koff;
    C += (long long)blockIdx.z * c_zstride;

    // ---- tile loader ----
    auto load_tiles = [&](int c, int s) {
        const float* Ab = A + (size_t)m0 * lda + (size_t)c * BK;
        const float* Bb = B + (size_t)c * BK;
        const uint32_t sAa = smem_u32(sA + s * A_STAGE);
        const uint32_t sBa = smem_u32(sB + s * B_STAGE);
        #pragma unroll
        for (int q = 0; q < 4; ++q) {                // A: 128 rows x 8 f4
            int idx = tid + q * 256;
            int r = idx >> 3, j = idx & 7;
            const float* gp = Ab + (size_t)r * lda + j * 4;
            uint32_t da = sAa + (uint32_t)(r * LDS_F + j * 4) * 4;
            asm volatile("cp.async.cg.shared.global [%0], [%1], 16;"
                         :: "r"(da), "l"(gp) : "memory");
        }
        #pragma unroll
        for (int q = 0; q < 8; ++q) {                // B: 256 rows x 8 f4
            int idx = tid + q * 256;
            int r = idx >> 3, j = idx & 7;
            int gn = n0 + r;
            int ok = (gn < nvalidB);
            const float* gq = Bb + (size_t)(ok ? gn : 0) * ldb + j * 4;
            uint32_t db = sBa + (uint32_t)(r * LDS_F + j * 4) * 4;
            int sz = ok ? 16 : 0;
            asm volatile("cp.async.cg.shared.global [%0], [%1], 16, %2;"
                         :: "r"(db), "l"(gq), "r"(sz) : "memory");
        }
        asm volatile("cp.async.commit_group;" ::: "memory");
    };

    float acc[4][8][4];
    #pragma unroll
    for (int i = 0; i < 4; ++i)
        #pragma unroll
        for (int j = 0; j < 8; ++j)
            #pragma unroll
            for (int k = 0; k < 4; ++k) acc[i][j][k] = 0.f;

    const int NCH = Kps / BK;
    load_tiles(0, 0);
    if (NCH > 1) load_tiles(1, 1);

    for (int c = 0; c < NCH; ++c) {
        if (c + 1 < NCH) {
            asm volatile("cp.async.wait_group 1;" ::: "memory");
        } else {
            asm volatile("cp.async.wait_group 0;" ::: "memory");
        }
        __syncthreads();
        if (c + 2 < NCH) load_tiles(c + 2, (c + 2) % NSTAGE);

        const int s = c % NSTAGE;
        const uint32_t* tA = reinterpret_cast<const uint32_t*>(sA + s * A_STAGE);
        const uint32_t* tB = reinterpret_cast<const uint32_t*>(sB + s * B_STAGE);

        #pragma unroll
        for (int ks = 0; ks < 4; ++ks) {
            const int kb = ks * 8;
            uint32_t bf[8][2];
            #pragma unroll
            for (int ni = 0; ni < 8; ++ni) {
                int col = wn * 64 + ni * 8 + g;
                bf[ni][0] = tB[col * LDS_F + kb + t];
                bf[ni][1] = tB[col * LDS_F + kb + t + 4];
            }
            #pragma unroll
            for (int mi = 0; mi < 4; ++mi) {
                int rr = wm * 64 + mi * 16 + g;
                uint32_t a0 = tA[rr * LDS_F + kb + t];
                uint32_t a1 = tA[(rr + 8) * LDS_F + kb + t];
                uint32_t a2 = tA[rr * LDS_F + kb + t + 4];
                uint32_t a3 = tA[(rr + 8) * LDS_F + kb + t + 4];
                #pragma unroll
                for (int ni = 0; ni < 8; ++ni)
                    mma_tf32(acc[mi][ni], a0, a1, a2, a3, bf[ni][0], bf[ni][1]);
            }
        }
        __syncthreads();
    }

    // ---- epilogue ----
    #pragma unroll
    for (int mi = 0; mi < 4; ++mi) {
        const int rr = m0 + wm * 64 + mi * 16 + g;
        #pragma unroll
        for (int ni = 0; ni < 8; ++ni) {
            const int col = n0 + wn * 64 + ni * 8 + 2 * t;
            float v0 = acc[mi][ni][0], v1 = acc[mi][ni][1];
            float v2 = acc[mi][ni][2], v3 = acc[mi][ni][3];
            if (epi_mode == 0) {
                float b0 = (col     < nvalidB) ? aux[col]     : 0.f;
                float b1 = (col + 1 < nvalidB) ? aux[col + 1] : 0.f;
                v0 += b0; v1 += b1; v2 += b0; v3 += b1;
                if (col     >= nvalidB) { v0 = -1e30f; v2 = -1e30f; }
                if (col + 1 >= nvalidB) { v1 = -1e30f; v3 = -1e30f; }
            } else if (epi_mode == 2) {
                float b0 = aux[col], b1 = aux[col + 1];
                v0 += b0; v1 += b1; v2 += b0; v3 += b1;
            }
            *reinterpret_cast<float2*>(C + (size_t)rr * ldc + col) =
                make_float2(v0, v1);
            *reinterpret_cast<float2*>(C + (size_t)(rr + 8) * ldc + col) =
                make_float2(v2, v3);
        }
    }
}

// ============================================================================
// prep: rounded copy (float4 granularity, n % 1024 == 0)
// ============================================================================
__global__ void __launch_bounds__(256)
round_copy(const float* __restrict__ in, float* __restrict__ out)
{
    int i = blockIdx.x * 1024 + threadIdx.x * 4;
    float4 v = *reinterpret_cast<const float4*>(in + i);
    v.x = tf32r(v.x); v.y = tf32r(v.y); v.z = tf32r(v.z); v.w = tf32r(v.w);
    *reinterpret_cast<float4*>(out + i) = v;
}

// ============================================================================
// WvT[d, v] = round(Wv[v, d]) (padded to VPAD);  wvr = round(Wv)
// ============================================================================
__global__ void __launch_bounds__(256)
transpose_wv(const float* __restrict__ Wv, float* __restrict__ WvT,
             float* __restrict__ wvr)
{
    __shared__ float tt[32][33];
    const int v0 = blockIdx.x * 32;
    const int d0 = blockIdx.y * 32;
    const int tx = threadIdx.x & 31;
    const int ty = threadIdx.x >> 5;     // 0..7
    #pragma unroll
    for (int i = 0; i < 32; i += 8) {
        int v = v0 + ty + i;
        float val = 0.f;
        if (v < VOCAB) {
            val = tf32r(Wv[(size_t)v * DDIM + d0 + tx]);
            wvr[(size_t)v * DDIM + d0 + tx] = val;
        }
        tt[ty + i][tx] = val;
    }
    __syncthreads();
    #pragma unroll
    for (int i = 0; i < 32; i += 8)
        WvT[(size_t)(d0 + ty + i) * VPAD + v0 + tx] = tt[tx][ty + i];
}

// ============================================================================
// Row softmax: online (m, l), write p = round(exp(x - m) / l) in place.
// ============================================================================
__global__ void __launch_bounds__(256)
softmax_rows(float* __restrict__ L)
{
    __shared__ float sm_m[256], sm_s[256];
    const int row = blockIdx.x;
    float* rp = L + (size_t)row * VPAD;
    const int tid = threadIdx.x;

    float m = -3.0e38f, s = 0.f;
    for (int i = tid; i < VPAD / 4; i += 256) {
        float4 v = reinterpret_cast<const float4*>(rp)[i];
        float xs[4] = {v.x, v.y, v.z, v.w};
        #pragma unroll
        for (int q = 0; q < 4; ++q) {
            float x = xs[q];
            if (x > m) { s = s * __expf(m - x) + 1.f; m = x; }
            else       { s += __expf(x - m); }
        }
    }
    sm_m[tid] = m; sm_s[tid] = s;
    __syncthreads();
    for (int off = 128; off > 0; off >>= 1) {
        if (tid < off) {
            float m2 = sm_m[tid + off], s2 = sm_s[tid + off];
            float m1 = sm_m[tid],       s1 = sm_s[tid];
            float M = fmaxf(m1, m2);
            sm_s[tid] = s1 * __expf(m1 - M) + s2 * __expf(m2 - M);
            sm_m[tid] = M;
        }
        __syncthreads();
    }
    const float M = sm_m[0];
    const float R = 1.0f / sm_s[0];

    for (int i = tid; i < VPAD / 4; i += 256) {
        float4 v = reinterpret_cast<const float4*>(rp)[i];
        v.x = tf32r(__expf(v.x - M) * R);
        v.y = tf32r(__expf(v.y - M) * R);
        v.z = tf32r(__expf(v.z - M) * R);
        v.w = tf32r(__expf(v.w - M) * R);
        reinterpret_cast<float4*>(rp)[i] = v;
    }
}

// ============================================================================
// split-K reduction: h = round(sum_z hp[z])
// ============================================================================
__global__ void __launch_bounds__(256)
reduce_splitk(const float* __restrict__ hp, float* __restrict__ h)
{
    const size_t MD = (size_t)MROWS * DDIM;
    int i = blockIdx.x * 1024 + threadIdx.x * 4;
    float4 a = *reinterpret_cast<const float4*>(hp + i);
    #pragma unroll
    for (int z = 1; z < SPLITK; ++z) {
        float4 b = *reinterpret_cast<const float4*>(hp + z * MD + i);
        a.x += b.x; a.y += b.y; a.z += b.z; a.w += b.w;
    }
    a.x = tf32r(a.x); a.y = tf32r(a.y); a.z = tf32r(a.z); a.w = tf32r(a.w);
    *reinterpret_cast<float4*>(h + i) = a;
}

// ============================================================================
// host launcher
// ============================================================================
extern "C" void kernel_launch(void* const* d_in, const int* in_sizes, int n_in,
                              void* d_out, int out_size)
{
    const float* x  = (const float*)d_in[0];
    const float* Wv = (const float*)d_in[1];
    const float* bv = (const float*)d_in[2];
    const float* Wl = (const float*)d_in[3];
    const float* bl = (const float*)d_in[4];
    float* out = (float*)d_out;

    void *p_probs, *p_wvt, *p_wvr, *p_xr, *p_wlr, *p_hp, *p_h;
    cudaGetSymbolAddress(&p_probs, g_probs);
    cudaGetSymbolAddress(&p_wvt,   g_wvt);
    cudaGetSymbolAddress(&p_wvr,   g_wvr);
    cudaGetSymbolAddress(&p_xr,    g_xr);
    cudaGetSymbolAddress(&p_wlr,   g_wlr);
    cudaGetSymbolAddress(&p_hp,    g_hp);
    cudaGetSymbolAddress(&p_h,     g_h);
    float* probs = (float*)p_probs;
    float* wvt   = (float*)p_wvt;
    float* wvr   = (float*)p_wvr;
    float* xr    = (float*)p_xr;
    float* wlr   = (float*)p_wlr;
    float* hp    = (float*)p_hp;
    float* h     = (float*)p_h;

    static bool attr_set = false;
    if (!attr_set) {
        cudaFuncSetAttribute(gemm_tn,
            cudaFuncAttributeMaxDynamicSharedMemorySize, GEMM_SMEM);
        attr_set = true;
    }

    // 1) prep: round x, Wl; round+transpose Wv
    round_copy<<<MROWS * DDIM / 1024, 256>>>(x, xr);
    round_copy<<<DDIM * DDIM / 1024, 256>>>(Wl, wlr);
    transpose_wv<<<dim3(VPAD / 32, DDIM / 32), 256>>>(Wv, wvt, wvr);

    // 2) logits = xr @ wvr^T + bv
    gemm_tn<<<dim3(MROWS / 128, VPAD / 256, 1), 256, GEMM_SMEM>>>(
        xr, DDIM, wvr, DDIM, probs, VPAD, 0, DDIM, VOCAB, bv, 0);

    // 3) softmax in place (rounded probs)
    softmax_rows<<<MROWS, 256>>>(probs);

    // 4) hp[z] = p @ wvt^T (split-K), then h = round(sum)
    gemm_tn<<<dim3(MROWS / 128, DDIM / 256, SPLITK), 256, GEMM_SMEM>>>(
        probs, VPAD, wvt, VPAD, hp, DDIM, (long long)MROWS * DDIM,
        KSPLIT, DDIM, nullptr, 3);
    reduce_splitk<<<MROWS * DDIM / 1024, 256>>>(hp, h);

    // 5) out = h @ wlr^T + bl
    gemm_tn<<<dim3(MROWS / 128, DDIM / 256, 1), 256, GEMM_SMEM>>>(
        h, DDIM, wlr, DDIM, out, DDIM, 0, DDIM, DDIM, bl, 2);
}